// round 1
// baseline (speedup 1.0000x reference)
#include <cuda_runtime.h>
#include <math.h>

// Problem dims (fixed by the dataset)
#define Q   512
#define D   131072           // 512*16*16
#define D4  (D/4)
#define B   2
#define A   16
#define C   19
#define HW  65536            // 256*256
#define REFINE_CONF 0.968f

// ---------------- scratch (no allocations allowed) ----------------
__device__ float g_qq[Q];          // ||queue_q||^2
__device__ float g_qt[Q][B];       // queue_q . tgt_b
__device__ float g_tt[B];          // ||tgt_b||^2
__device__ int   g_imin[B];
__device__ float g_cd2[B];         // closest distance^2
__device__ float g_d2[B][A];       // ||aug - closest||^2
__device__ int   g_selidx[B][16];
__device__ int   g_selcnt[B];      // min(mask count, k)
__device__ int   g_mcnt[B];        // mask count

// ---------------- kernel 1: queue dots (the 256MB read) ----------------
// 4 queue rows per block; 128 blocks x 512 threads. tgt rows stay hot in L2.
__global__ __launch_bounds__(512) void k_dots(const float* __restrict__ queue,
                                              const float* __restrict__ tgt) {
    const int q0 = blockIdx.x * 4;
    const int tid = threadIdx.x;
    const float4* __restrict__ qf = (const float4*)queue;
    const float4* __restrict__ tf = (const float4*)tgt;

    float qq[4] = {0.f, 0.f, 0.f, 0.f};
    float qt0[4] = {0.f, 0.f, 0.f, 0.f};
    float qt1[4] = {0.f, 0.f, 0.f, 0.f};

    for (int i = tid; i < D4; i += 512) {
        float4 t0 = tf[i];
        float4 t1 = tf[D4 + i];
#pragma unroll
        for (int r = 0; r < 4; r++) {
            float4 qv = qf[(size_t)(q0 + r) * D4 + i];
            qq[r]  = fmaf(qv.x, qv.x, fmaf(qv.y, qv.y, fmaf(qv.z, qv.z, fmaf(qv.w, qv.w, qq[r]))));
            qt0[r] = fmaf(qv.x, t0.x, fmaf(qv.y, t0.y, fmaf(qv.z, t0.z, fmaf(qv.w, t0.w, qt0[r]))));
            qt1[r] = fmaf(qv.x, t1.x, fmaf(qv.y, t1.y, fmaf(qv.z, t1.z, fmaf(qv.w, t1.w, qt1[r]))));
        }
    }

    // block reduce 12 values
    float v[12];
#pragma unroll
    for (int r = 0; r < 4; r++) { v[r*3] = qq[r]; v[r*3+1] = qt0[r]; v[r*3+2] = qt1[r]; }

    __shared__ float red[16][12];
    const int lane = tid & 31, warp = tid >> 5;
#pragma unroll
    for (int j = 0; j < 12; j++)
#pragma unroll
        for (int o = 16; o > 0; o >>= 1)
            v[j] += __shfl_down_sync(0xFFFFFFFFu, v[j], o);
    if (lane == 0)
#pragma unroll
        for (int j = 0; j < 12; j++) red[warp][j] = v[j];
    __syncthreads();
    if (tid < 16) {
#pragma unroll
        for (int j = 0; j < 12; j++) v[j] = red[tid][j];
#pragma unroll
        for (int j = 0; j < 12; j++)
#pragma unroll
            for (int o = 8; o > 0; o >>= 1)
                v[j] += __shfl_down_sync(0xFFFFu, v[j], o);
        if (tid == 0) {
#pragma unroll
            for (int r = 0; r < 4; r++) {
                g_qq[q0 + r]    = v[r*3];
                g_qt[q0 + r][0] = v[r*3+1];
                g_qt[q0 + r][1] = v[r*3+2];
            }
        }
    }
}

// ---------------- kernel 2a: ||tgt_b||^2 ----------------
__global__ __launch_bounds__(256) void k_tt(const float* __restrict__ tgt) {
    const int b = blockIdx.x;
    const int tid = threadIdx.x;
    const float4* __restrict__ tf = (const float4*)(tgt + (size_t)b * D);
    float s = 0.f;
    for (int i = tid; i < D4; i += 256) {
        float4 t = tf[i];
        s = fmaf(t.x, t.x, fmaf(t.y, t.y, fmaf(t.z, t.z, fmaf(t.w, t.w, s))));
    }
    __shared__ float red[8];
    const int lane = tid & 31, warp = tid >> 5;
#pragma unroll
    for (int o = 16; o > 0; o >>= 1) s += __shfl_down_sync(0xFFFFFFFFu, s, o);
    if (lane == 0) red[warp] = s;
    __syncthreads();
    if (tid < 8) {
        s = red[tid];
#pragma unroll
        for (int o = 4; o > 0; o >>= 1) s += __shfl_down_sync(0xFFu, s, o);
        if (tid == 0) g_tt[b] = s;
    }
}

// ---------------- kernel 2b: argmin over Q (stable, first index on tie) ----------------
__global__ __launch_bounds__(512) void k_argmin() {
    const int tid = threadIdx.x;   // == q, Q == 512
    __shared__ float sval[512];
    __shared__ int   sidx[512];
    for (int b = 0; b < B; b++) {
        float v = g_qq[tid] - 2.0f * g_qt[tid][b] + g_tt[b];
        sval[tid] = v; sidx[tid] = tid;
        __syncthreads();
        for (int s = 256; s > 0; s >>= 1) {
            if (tid < s) {
                float ov = sval[tid + s]; int oi = sidx[tid + s];
                if (ov < sval[tid] || (ov == sval[tid] && oi < sidx[tid])) {
                    sval[tid] = ov; sidx[tid] = oi;
                }
            }
            __syncthreads();
        }
        if (tid == 0) { g_imin[b] = sidx[0]; g_cd2[b] = sval[0]; }
        __syncthreads();
    }
}

// ---------------- kernel 3: ||aug[b,a] - closest_b||^2 ----------------
__global__ __launch_bounds__(512) void k_d2(const float* __restrict__ auged,
                                            const float* __restrict__ queue) {
    const int b = blockIdx.x / A;
    const int a = blockIdx.x % A;
    const int tid = threadIdx.x;
    const int im = g_imin[b];
    const float4* __restrict__ af = (const float4*)(auged + ((size_t)b * A + a) * D);
    const float4* __restrict__ cf = (const float4*)(queue + (size_t)im * D);
    float s = 0.f;
    for (int i = tid; i < D4; i += 512) {
        float4 av = af[i];
        float4 cv = cf[i];
        float dx = av.x - cv.x, dy = av.y - cv.y, dz = av.z - cv.z, dw = av.w - cv.w;
        s = fmaf(dx, dx, fmaf(dy, dy, fmaf(dz, dz, fmaf(dw, dw, s))));
    }
    __shared__ float red[16];
    const int lane = tid & 31, warp = tid >> 5;
#pragma unroll
    for (int o = 16; o > 0; o >>= 1) s += __shfl_down_sync(0xFFFFFFFFu, s, o);
    if (lane == 0) red[warp] = s;
    __syncthreads();
    if (tid < 16) {
        s = red[tid];
#pragma unroll
        for (int o = 8; o > 0; o >>= 1) s += __shfl_down_sync(0xFFFFu, s, o);
        if (tid == 0) g_d2[b][a] = s;
    }
}

// ---------------- kernel 4: masked top-k selection (serial, stable) ----------------
__global__ void k_select(const int* __restrict__ kptr) {
    int k = kptr ? kptr[0] : 5;
    if (k > 16) k = 16;
    if (k < 0)  k = 0;
    for (int b = 0; b < B; b++) {
        float cd = g_cd2[b];
        float dv[16];
        int m = 0;
#pragma unroll
        for (int a = 0; a < A; a++) {
            dv[a] = g_d2[b][a];
            if (dv[a] <= cd) m++;
        }
        bool used[16] = {false};
        int cnt = 0;
        for (int j = 0; j < k; j++) {
            int best = -1; float bv = INFINITY;
            for (int a = 0; a < A; a++) {
                if (!used[a] && dv[a] <= cd && dv[a] < bv) { bv = dv[a]; best = a; }
            }
            if (best < 0) break;
            used[best] = true;
            g_selidx[b][cnt++] = best;
        }
        g_selcnt[b] = cnt;
        g_mcnt[b]   = m;
    }
}

// ---------------- kernel 5: fused softmax-avg / argmax / confidence gate ----------------
__global__ __launch_bounds__(256) void k_final(const float* __restrict__ auged_logits,
                                               const float* __restrict__ tgt_logits,
                                               const int*   __restrict__ pseudo,
                                               float* __restrict__ out) {
    const int pix = blockIdx.x * 256 + threadIdx.x;   // < B*HW
    const int b = pix >> 16;
    const int p = pix & (HW - 1);

    const int cnt = g_selcnt[b];
    const int m   = g_mcnt[b];

    float acc[C];
#pragma unroll
    for (int c = 0; c < C; c++) acc[c] = 0.f;

    for (int j = 0; j < cnt; j++) {
        const int a = g_selidx[b][j];
        const float* __restrict__ lp = auged_logits + ((size_t)(b * A + a) * C) * HW + p;
        float l[C];
        float mx = -INFINITY;
#pragma unroll
        for (int c = 0; c < C; c++) { l[c] = lp[(size_t)c * HW]; mx = fmaxf(mx, l[c]); }
        float s = 0.f;
#pragma unroll
        for (int c = 0; c < C; c++) { l[c] = __expf(l[c] - mx); s += l[c]; }
        float inv = 1.0f / s;
#pragma unroll
        for (int c = 0; c < C; c++) acc[c] = fmaf(l[c], inv, acc[c]);
    }

    const float invc = 1.0f / (float)max(cnt, 1);

    // knn label = argmax over averaged softmax (first index on tie)
    int knn = 0; float bv = acc[0];
#pragma unroll
    for (int c = 1; c < C; c++) { if (acc[c] > bv) { bv = acc[c]; knn = c; } }

    // target confidence: max softmax prob = 1 / sum(exp(l - max))
    {
        const float* __restrict__ tp = tgt_logits + (size_t)b * C * HW + p;
        float mx = -INFINITY;
        float l[C];
#pragma unroll
        for (int c = 0; c < C; c++) { l[c] = tp[(size_t)c * HW]; mx = fmaxf(mx, l[c]); }
        float s = 0.f;
#pragma unroll
        for (int c = 0; c < C; c++) s += expf(l[c] - mx);
        float maxprob = 1.0f / s;
        bool pmask = maxprob < REFINE_CONF;

        int pl = pseudo[(size_t)b * HW + p];
        int refined = (pmask && m > 0) ? knn : pl;
        out[pix] = (float)refined;
    }

    // avg_soft output
    float* __restrict__ oavg = out + (size_t)B * HW;
#pragma unroll
    for (int c = 0; c < C; c++)
        oavg[((size_t)b * C + c) * HW + p] = acc[c] * invc;
}

// ---------------- launch ----------------
extern "C" void kernel_launch(void* const* d_in, const int* in_sizes, int n_in,
                              void* d_out, int out_size) {
    const float* source_queue = (const float*)d_in[0];
    const float* tgt_feat     = (const float*)d_in[1];
    const float* tgt_logits   = (const float*)d_in[2];
    const float* auged_feat   = (const float*)d_in[3];
    const float* auged_logits = (const float*)d_in[4];
    const int*   pseudo_label = (const int*)d_in[5];
    const int*   kptr         = (n_in > 6) ? (const int*)d_in[6] : nullptr;
    float* out = (float*)d_out;

    k_dots  <<<Q / 4, 512>>>(source_queue, tgt_feat);
    k_tt    <<<B, 256>>>(tgt_feat);
    k_argmin<<<1, 512>>>();
    k_d2    <<<B * A, 512>>>(auged_feat, source_queue);
    k_select<<<1, 1>>>(kptr);
    k_final <<<(B * HW) / 256, 256>>>(auged_logits, tgt_logits, pseudo_label, out);
    (void)in_sizes; (void)out_size;
}

// round 2
// speedup vs baseline: 1.2695x; 1.2695x over previous
#include <cuda_runtime.h>
#include <math.h>

// Problem dims (fixed by the dataset)
#define Q   512
#define D   131072           // 512*16*16
#define D4  (D/4)            // 32768 float4
#define B   2
#define A   16
#define C   19
#define HW  65536            // 256*256
#define REFINE_CONF 0.968f

#define S_DOTS 8             // D-splits for k_dots  -> grid 128*8 = 1024
#define S_D2   16            // D-splits for k_d2    -> grid 32*16 = 512

// ---------------- scratch (no allocations allowed) ----------------
__device__ float g_pqq[S_DOTS][Q];        // partial ||queue_q||^2
__device__ float g_pqt[S_DOTS][Q][B];     // partial queue_q . tgt_b
__device__ float g_tt[B];                 // ||tgt_b||^2
__device__ int   g_imin[B];
__device__ float g_cd2[B];                // closest distance^2
__device__ float g_pd2[S_D2][B][A];       // partial ||aug - closest||^2
__device__ int   g_selidx[B][16];
__device__ int   g_selcnt[B];             // #selected (<= k)
__device__ int   g_mcnt[B];               // mask count

// ---------------- kernel 1: queue dots, split along D ----------------
// grid = S_DOTS * 128 blocks x 512 threads; 4 rows per block, D/S_DOTS cols.
__global__ __launch_bounds__(512) void k_dots(const float* __restrict__ queue,
                                              const float* __restrict__ tgt) {
    const int s      = blockIdx.x >> 7;          // D-split  (same-s blocks adjacent -> tgt chunk L2 reuse)
    const int rowgrp = blockIdx.x & 127;
    const int q0  = rowgrp * 4;
    const int tid = threadIdx.x;
    const int i0  = s * (D4 / S_DOTS);           // 4096 float4 per split
    const int i1  = i0 + (D4 / S_DOTS);

    const float4* __restrict__ qf = (const float4*)queue;
    const float4* __restrict__ tf = (const float4*)tgt;

    float qq[4]  = {0.f, 0.f, 0.f, 0.f};
    float qt0[4] = {0.f, 0.f, 0.f, 0.f};
    float qt1[4] = {0.f, 0.f, 0.f, 0.f};

    for (int i = i0 + tid; i < i1; i += 512) {
        float4 t0 = tf[i];
        float4 t1 = tf[D4 + i];
#pragma unroll
        for (int r = 0; r < 4; r++) {
            float4 qv = qf[(size_t)(q0 + r) * D4 + i];
            qq[r]  = fmaf(qv.x, qv.x, fmaf(qv.y, qv.y, fmaf(qv.z, qv.z, fmaf(qv.w, qv.w, qq[r]))));
            qt0[r] = fmaf(qv.x, t0.x, fmaf(qv.y, t0.y, fmaf(qv.z, t0.z, fmaf(qv.w, t0.w, qt0[r]))));
            qt1[r] = fmaf(qv.x, t1.x, fmaf(qv.y, t1.y, fmaf(qv.z, t1.z, fmaf(qv.w, t1.w, qt1[r]))));
        }
    }

    // block reduce 12 values
    float v[12];
#pragma unroll
    for (int r = 0; r < 4; r++) { v[r*3] = qq[r]; v[r*3+1] = qt0[r]; v[r*3+2] = qt1[r]; }

    __shared__ float red[16][12];
    const int lane = tid & 31, warp = tid >> 5;
#pragma unroll
    for (int j = 0; j < 12; j++)
#pragma unroll
        for (int o = 16; o > 0; o >>= 1)
            v[j] += __shfl_down_sync(0xFFFFFFFFu, v[j], o);
    if (lane == 0)
#pragma unroll
        for (int j = 0; j < 12; j++) red[warp][j] = v[j];
    __syncthreads();
    if (tid < 16) {
#pragma unroll
        for (int j = 0; j < 12; j++) v[j] = red[tid][j];
#pragma unroll
        for (int j = 0; j < 12; j++)
#pragma unroll
            for (int o = 8; o > 0; o >>= 1)
                v[j] += __shfl_down_sync(0xFFFFu, v[j], o);
        if (tid == 0) {
#pragma unroll
            for (int r = 0; r < 4; r++) {
                g_pqq[s][q0 + r]    = v[r*3];
                g_pqt[s][q0 + r][0] = v[r*3+1];
                g_pqt[s][q0 + r][1] = v[r*3+2];
            }
        }
    }
}

// ---------------- kernel 2a: ||tgt_b||^2 (tiny) ----------------
__global__ __launch_bounds__(256) void k_tt(const float* __restrict__ tgt) {
    const int b = blockIdx.x;
    const int tid = threadIdx.x;
    const float4* __restrict__ tf = (const float4*)(tgt + (size_t)b * D);
    float s = 0.f;
    for (int i = tid; i < D4; i += 256) {
        float4 t = tf[i];
        s = fmaf(t.x, t.x, fmaf(t.y, t.y, fmaf(t.z, t.z, fmaf(t.w, t.w, s))));
    }
    __shared__ float red[8];
    const int lane = tid & 31, warp = tid >> 5;
#pragma unroll
    for (int o = 16; o > 0; o >>= 1) s += __shfl_down_sync(0xFFFFFFFFu, s, o);
    if (lane == 0) red[warp] = s;
    __syncthreads();
    if (tid < 8) {
        s = red[tid];
#pragma unroll
        for (int o = 4; o > 0; o >>= 1) s += __shfl_down_sync(0xFFu, s, o);
        if (tid == 0) g_tt[b] = s;
    }
}

// ---------------- kernel 2b: reduce partials + argmin (stable) ----------------
__global__ __launch_bounds__(512) void k_reduce_argmin() {
    const int tid = threadIdx.x;   // == q, Q == 512
    float qq = 0.f, qt0 = 0.f, qt1 = 0.f;
#pragma unroll
    for (int s = 0; s < S_DOTS; s++) {
        qq  += g_pqq[s][tid];
        qt0 += g_pqt[s][tid][0];
        qt1 += g_pqt[s][tid][1];
    }
    __shared__ float sval[512];
    __shared__ int   sidx[512];
    for (int b = 0; b < B; b++) {
        float qt = (b == 0) ? qt0 : qt1;
        float v = qq - 2.0f * qt + g_tt[b];
        sval[tid] = v; sidx[tid] = tid;
        __syncthreads();
        for (int s = 256; s > 0; s >>= 1) {
            if (tid < s) {
                float ov = sval[tid + s]; int oi = sidx[tid + s];
                if (ov < sval[tid] || (ov == sval[tid] && oi < sidx[tid])) {
                    sval[tid] = ov; sidx[tid] = oi;
                }
            }
            __syncthreads();
        }
        if (tid == 0) { g_imin[b] = sidx[0]; g_cd2[b] = sval[0]; }
        __syncthreads();
    }
}

// ---------------- kernel 3: ||aug[b,a] - closest_b||^2, split along D ----------------
__global__ __launch_bounds__(512) void k_d2(const float* __restrict__ auged,
                                            const float* __restrict__ queue) {
    const int pair = blockIdx.x & 31;            // b*A + a
    const int s    = blockIdx.x >> 5;
    const int b = pair >> 4;
    const int a = pair & 15;
    const int tid = threadIdx.x;
    const int im = g_imin[b];
    const int i0 = s * (D4 / S_D2);              // 2048 float4 per split
    const int i1 = i0 + (D4 / S_D2);

    const float4* __restrict__ af = (const float4*)(auged + ((size_t)b * A + a) * D);
    const float4* __restrict__ cf = (const float4*)(queue + (size_t)im * D);
    float sacc = 0.f;
    for (int i = i0 + tid; i < i1; i += 512) {
        float4 av = af[i];
        float4 cv = cf[i];
        float dx = av.x - cv.x, dy = av.y - cv.y, dz = av.z - cv.z, dw = av.w - cv.w;
        sacc = fmaf(dx, dx, fmaf(dy, dy, fmaf(dz, dz, fmaf(dw, dw, sacc))));
    }
    __shared__ float red[16];
    const int lane = tid & 31, warp = tid >> 5;
#pragma unroll
    for (int o = 16; o > 0; o >>= 1) sacc += __shfl_down_sync(0xFFFFFFFFu, sacc, o);
    if (lane == 0) red[warp] = sacc;
    __syncthreads();
    if (tid < 16) {
        sacc = red[tid];
#pragma unroll
        for (int o = 8; o > 0; o >>= 1) sacc += __shfl_down_sync(0xFFFFu, sacc, o);
        if (tid == 0) g_pd2[s][b][a] = sacc;
    }
}

// ---------------- kernel 4: reduce d2 + masked top-k selection (1 warp) ----------------
__global__ void k_select(const int* __restrict__ kptr) {
    const int tid = threadIdx.x;   // 32 threads
    __shared__ float d2s[B][A];
    if (tid < B * A) {
        const int b = tid >> 4, a = tid & 15;
        float v = 0.f;
#pragma unroll
        for (int s = 0; s < S_D2; s++) v += g_pd2[s][b][a];
        d2s[b][a] = v;
    }
    __syncwarp();
    if (tid == 0) {
        int k = kptr ? kptr[0] : 5;
        if (k > 16) k = 16;
        if (k < 0)  k = 0;
        for (int b = 0; b < B; b++) {
            float cd = g_cd2[b];
            float dv[16];
            int m = 0;
#pragma unroll
            for (int a = 0; a < A; a++) {
                dv[a] = d2s[b][a];
                if (dv[a] <= cd) m++;
            }
            bool used[16] = {false};
            int cnt = 0;
            for (int j = 0; j < k; j++) {
                int best = -1; float bv = INFINITY;
                for (int a = 0; a < A; a++) {
                    if (!used[a] && dv[a] <= cd && dv[a] < bv) { bv = dv[a]; best = a; }
                }
                if (best < 0) break;
                used[best] = true;
                g_selidx[b][cnt++] = best;
            }
            g_selcnt[b] = cnt;
            g_mcnt[b]   = m;
        }
    }
}

// ---------------- kernel 5: fused softmax-avg / argmax / confidence gate ----------------
__global__ __launch_bounds__(256) void k_final(const float* __restrict__ auged_logits,
                                               const float* __restrict__ tgt_logits,
                                               const int*   __restrict__ pseudo,
                                               float* __restrict__ out) {
    const int pix = blockIdx.x * 256 + threadIdx.x;   // < B*HW
    const int b = pix >> 16;
    const int p = pix & (HW - 1);

    const int cnt = g_selcnt[b];
    const int m   = g_mcnt[b];

    float acc[C];
#pragma unroll
    for (int c = 0; c < C; c++) acc[c] = 0.f;

    for (int j = 0; j < cnt; j++) {
        const int a = g_selidx[b][j];
        const float* __restrict__ lp = auged_logits + ((size_t)(b * A + a) * C) * HW + p;
        float l[C];
        float mx = -INFINITY;
#pragma unroll
        for (int c = 0; c < C; c++) { l[c] = lp[(size_t)c * HW]; mx = fmaxf(mx, l[c]); }
        float s = 0.f;
#pragma unroll
        for (int c = 0; c < C; c++) { l[c] = __expf(l[c] - mx); s += l[c]; }
        float inv = 1.0f / s;
#pragma unroll
        for (int c = 0; c < C; c++) acc[c] = fmaf(l[c], inv, acc[c]);
    }

    const float invc = 1.0f / (float)max(cnt, 1);

    // knn label = argmax over averaged softmax (first index on tie)
    int knn = 0; float bv = acc[0];
#pragma unroll
    for (int c = 1; c < C; c++) { if (acc[c] > bv) { bv = acc[c]; knn = c; } }

    // target confidence: max softmax prob = 1 / sum(exp(l - max))
    {
        const float* __restrict__ tp = tgt_logits + (size_t)b * C * HW + p;
        float mx = -INFINITY;
        float l[C];
#pragma unroll
        for (int c = 0; c < C; c++) { l[c] = tp[(size_t)c * HW]; mx = fmaxf(mx, l[c]); }
        float s = 0.f;
#pragma unroll
        for (int c = 0; c < C; c++) s += expf(l[c] - mx);
        float maxprob = 1.0f / s;
        bool pmask = maxprob < REFINE_CONF;

        int pl = pseudo[(size_t)b * HW + p];
        int refined = (pmask && m > 0) ? knn : pl;
        out[pix] = (float)refined;
    }

    // avg_soft output
    float* __restrict__ oavg = out + (size_t)B * HW;
#pragma unroll
    for (int c = 0; c < C; c++)
        oavg[((size_t)b * C + c) * HW + p] = acc[c] * invc;
}

// ---------------- launch ----------------
extern "C" void kernel_launch(void* const* d_in, const int* in_sizes, int n_in,
                              void* d_out, int out_size) {
    const float* source_queue = (const float*)d_in[0];
    const float* tgt_feat     = (const float*)d_in[1];
    const float* tgt_logits   = (const float*)d_in[2];
    const float* auged_feat   = (const float*)d_in[3];
    const float* auged_logits = (const float*)d_in[4];
    const int*   pseudo_label = (const int*)d_in[5];
    const int*   kptr         = (n_in > 6) ? (const int*)d_in[6] : nullptr;
    float* out = (float*)d_out;

    k_dots         <<<S_DOTS * 128, 512>>>(source_queue, tgt_feat);
    k_tt           <<<B, 256>>>(tgt_feat);
    k_reduce_argmin<<<1, 512>>>();
    k_d2           <<<32 * S_D2, 512>>>(auged_feat, source_queue);
    k_select       <<<1, 32>>>(kptr);
    k_final        <<<(B * HW) / 256, 256>>>(auged_logits, tgt_logits, pseudo_label, out);
    (void)in_sizes; (void)out_size;
}

// round 3
// speedup vs baseline: 1.4497x; 1.1419x over previous
#include <cuda_runtime.h>
#include <math.h>

// Problem dims (fixed by the dataset)
#define Q   512
#define D   131072           // 512*16*16
#define D4  (D/4)            // 32768 float4
#define B   2
#define A   16
#define C   19
#define HW  65536            // 256*256
#define REFINE_CONF 0.968f

#define S_DOTS 8             // D-splits for k_dots: chunk = 4096 float4
#define NROWG  (Q/2)         // 256 row-groups (2 rows each)
#define S_D2   16            // D-splits for k_d2: chunk = 2048 float4
#define S_TT   16            // D-splits for k_tt

// ---------------- scratch (no allocations allowed) ----------------
__device__ float g_pqq[S_DOTS][Q];        // partial ||queue_q||^2
__device__ float g_pqt[S_DOTS][Q][B];     // partial queue_q . tgt_b
__device__ float g_ptt[S_TT][B];          // partial ||tgt_b||^2
__device__ int   g_imin[B];
__device__ float g_cd2[B];                // closest distance^2
__device__ float g_pd2[S_D2][B][A];       // partial ||aug - closest||^2
__device__ int   g_selidx[B][16];
__device__ int   g_selcnt[B];             // #selected (<= k)
__device__ int   g_mcnt[B];               // mask count

// ---------------- kernel 1: queue dots, 2 rows/block, 256 thr, unroll x2 ----------------
// grid = S_DOTS * NROWG = 2048 blocks. s = blockIdx>>8 so concurrent blocks share tgt chunk.
__global__ __launch_bounds__(256) void k_dots(const float* __restrict__ queue,
                                              const float* __restrict__ tgt) {
    const int s      = blockIdx.x >> 8;          // D-split
    const int rowgrp = blockIdx.x & (NROWG - 1);
    const int q0  = rowgrp * 2;
    const int tid = threadIdx.x;
    const int i0  = s * (D4 / S_DOTS);           // 4096 float4 per split
    const int i1  = i0 + (D4 / S_DOTS);

    const float4* __restrict__ qf0 = (const float4*)queue + (size_t)q0 * D4;
    const float4* __restrict__ qf1 = qf0 + D4;
    const float4* __restrict__ tf  = (const float4*)tgt;

    float qq0 = 0.f, qq1 = 0.f;
    float qt00 = 0.f, qt01 = 0.f;    // row0 . tgt0/tgt1
    float qt10 = 0.f, qt11 = 0.f;    // row1 . tgt0/tgt1

    for (int i = i0 + tid; i < i1; i += 512) {
        // front-batch 8 independent loads (MLP_p1 = 8)
        float4 ta0 = tf[i];
        float4 ta1 = tf[D4 + i];
        float4 qa0 = qf0[i];
        float4 qa1 = qf1[i];
        float4 tb0 = tf[i + 256];
        float4 tb1 = tf[D4 + i + 256];
        float4 qb0 = qf0[i + 256];
        float4 qb1 = qf1[i + 256];

        qq0  = fmaf(qa0.x, qa0.x, fmaf(qa0.y, qa0.y, fmaf(qa0.z, qa0.z, fmaf(qa0.w, qa0.w, qq0))));
        qq1  = fmaf(qa1.x, qa1.x, fmaf(qa1.y, qa1.y, fmaf(qa1.z, qa1.z, fmaf(qa1.w, qa1.w, qq1))));
        qt00 = fmaf(qa0.x, ta0.x, fmaf(qa0.y, ta0.y, fmaf(qa0.z, ta0.z, fmaf(qa0.w, ta0.w, qt00))));
        qt01 = fmaf(qa0.x, ta1.x, fmaf(qa0.y, ta1.y, fmaf(qa0.z, ta1.z, fmaf(qa0.w, ta1.w, qt01))));
        qt10 = fmaf(qa1.x, ta0.x, fmaf(qa1.y, ta0.y, fmaf(qa1.z, ta0.z, fmaf(qa1.w, ta0.w, qt10))));
        qt11 = fmaf(qa1.x, ta1.x, fmaf(qa1.y, ta1.y, fmaf(qa1.z, ta1.z, fmaf(qa1.w, ta1.w, qt11))));

        qq0  = fmaf(qb0.x, qb0.x, fmaf(qb0.y, qb0.y, fmaf(qb0.z, qb0.z, fmaf(qb0.w, qb0.w, qq0))));
        qq1  = fmaf(qb1.x, qb1.x, fmaf(qb1.y, qb1.y, fmaf(qb1.z, qb1.z, fmaf(qb1.w, qb1.w, qq1))));
        qt00 = fmaf(qb0.x, tb0.x, fmaf(qb0.y, tb0.y, fmaf(qb0.z, tb0.z, fmaf(qb0.w, tb0.w, qt00))));
        qt01 = fmaf(qb0.x, tb1.x, fmaf(qb0.y, tb1.y, fmaf(qb0.z, tb1.z, fmaf(qb0.w, tb1.w, qt01))));
        qt10 = fmaf(qb1.x, tb0.x, fmaf(qb1.y, tb0.y, fmaf(qb1.z, tb0.z, fmaf(qb1.w, tb0.w, qt10))));
        qt11 = fmaf(qb1.x, tb1.x, fmaf(qb1.y, tb1.y, fmaf(qb1.z, tb1.z, fmaf(qb1.w, tb1.w, qt11))));
    }

    // block reduce 6 values
    float v[6] = {qq0, qq1, qt00, qt01, qt10, qt11};
    __shared__ float red[8][6];
    const int lane = tid & 31, warp = tid >> 5;
#pragma unroll
    for (int j = 0; j < 6; j++)
#pragma unroll
        for (int o = 16; o > 0; o >>= 1)
            v[j] += __shfl_down_sync(0xFFFFFFFFu, v[j], o);
    if (lane == 0)
#pragma unroll
        for (int j = 0; j < 6; j++) red[warp][j] = v[j];
    __syncthreads();
    if (tid < 8) {
#pragma unroll
        for (int j = 0; j < 6; j++) v[j] = red[tid][j];
#pragma unroll
        for (int j = 0; j < 6; j++)
#pragma unroll
            for (int o = 4; o > 0; o >>= 1)
                v[j] += __shfl_down_sync(0xFFu, v[j], o);
        if (tid == 0) {
            g_pqq[s][q0]        = v[0];
            g_pqq[s][q0 + 1]    = v[1];
            g_pqt[s][q0][0]     = v[2];
            g_pqt[s][q0][1]     = v[3];
            g_pqt[s][q0 + 1][0] = v[4];
            g_pqt[s][q0 + 1][1] = v[5];
        }
    }
}

// ---------------- kernel 2a: partial ||tgt_b||^2, 32 blocks ----------------
__global__ __launch_bounds__(128) void k_tt(const float* __restrict__ tgt) {
    const int b = blockIdx.x & 1;
    const int s = blockIdx.x >> 1;               // 0..S_TT-1
    const int tid = threadIdx.x;
    const int i0 = s * (D4 / S_TT);              // 2048 float4
    const int i1 = i0 + (D4 / S_TT);
    const float4* __restrict__ tf = (const float4*)(tgt + (size_t)b * D);
    float sum = 0.f;
    for (int i = i0 + tid; i < i1; i += 128) {
        float4 t = tf[i];
        sum = fmaf(t.x, t.x, fmaf(t.y, t.y, fmaf(t.z, t.z, fmaf(t.w, t.w, sum))));
    }
    __shared__ float red[4];
    const int lane = tid & 31, warp = tid >> 5;
#pragma unroll
    for (int o = 16; o > 0; o >>= 1) sum += __shfl_down_sync(0xFFFFFFFFu, sum, o);
    if (lane == 0) red[warp] = sum;
    __syncthreads();
    if (tid < 4) {
        sum = red[tid];
#pragma unroll
        for (int o = 2; o > 0; o >>= 1) sum += __shfl_down_sync(0xFu, sum, o);
        if (tid == 0) g_ptt[s][b] = sum;
    }
}

// ---------------- kernel 2b: reduce partials + argmin (stable, first idx on tie) ----------------
__global__ __launch_bounds__(512) void k_reduce_argmin() {
    const int tid = threadIdx.x;   // == q, Q == 512
    float qq = 0.f, qt0 = 0.f, qt1 = 0.f;
#pragma unroll
    for (int s = 0; s < S_DOTS; s++) {
        qq  += g_pqq[s][tid];
        qt0 += g_pqt[s][tid][0];
        qt1 += g_pqt[s][tid][1];
    }
    __shared__ float tts[B];
    if (tid < B) {
        float t = 0.f;
#pragma unroll
        for (int s = 0; s < S_TT; s++) t += g_ptt[s][tid];
        tts[tid] = t;
    }
    __shared__ float sval[512];
    __shared__ int   sidx[512];
    __syncthreads();
    for (int b = 0; b < B; b++) {
        float qt = (b == 0) ? qt0 : qt1;
        float v = qq - 2.0f * qt + tts[b];
        sval[tid] = v; sidx[tid] = tid;
        __syncthreads();
        for (int s = 256; s > 0; s >>= 1) {
            if (tid < s) {
                float ov = sval[tid + s]; int oi = sidx[tid + s];
                if (ov < sval[tid] || (ov == sval[tid] && oi < sidx[tid])) {
                    sval[tid] = ov; sidx[tid] = oi;
                }
            }
            __syncthreads();
        }
        if (tid == 0) { g_imin[b] = sidx[0]; g_cd2[b] = sval[0]; }
        __syncthreads();
    }
}

// ---------------- kernel 3: ||aug[b,a] - closest_b||^2, unroll x2, 256 thr ----------------
__global__ __launch_bounds__(256) void k_d2(const float* __restrict__ auged,
                                            const float* __restrict__ queue) {
    const int pair = blockIdx.x & 31;            // b*A + a
    const int s    = blockIdx.x >> 5;
    const int b = pair >> 4;
    const int a = pair & 15;
    const int tid = threadIdx.x;
    const int im = g_imin[b];
    const int i0 = s * (D4 / S_D2);              // 2048 float4 per split
    const int i1 = i0 + (D4 / S_D2);

    const float4* __restrict__ af = (const float4*)(auged + ((size_t)b * A + a) * D);
    const float4* __restrict__ cf = (const float4*)(queue + (size_t)im * D);
    float s0 = 0.f, s1 = 0.f;
    for (int i = i0 + tid; i < i1; i += 512) {
        float4 av0 = af[i];
        float4 cv0 = cf[i];
        float4 av1 = af[i + 256];
        float4 cv1 = cf[i + 256];
        float dx0 = av0.x - cv0.x, dy0 = av0.y - cv0.y, dz0 = av0.z - cv0.z, dw0 = av0.w - cv0.w;
        float dx1 = av1.x - cv1.x, dy1 = av1.y - cv1.y, dz1 = av1.z - cv1.z, dw1 = av1.w - cv1.w;
        s0 = fmaf(dx0, dx0, fmaf(dy0, dy0, fmaf(dz0, dz0, fmaf(dw0, dw0, s0))));
        s1 = fmaf(dx1, dx1, fmaf(dy1, dy1, fmaf(dz1, dz1, fmaf(dw1, dw1, s1))));
    }
    float sacc = s0 + s1;
    __shared__ float red[8];
    const int lane = tid & 31, warp = tid >> 5;
#pragma unroll
    for (int o = 16; o > 0; o >>= 1) sacc += __shfl_down_sync(0xFFFFFFFFu, sacc, o);
    if (lane == 0) red[warp] = sacc;
    __syncthreads();
    if (tid < 8) {
        sacc = red[tid];
#pragma unroll
        for (int o = 4; o > 0; o >>= 1) sacc += __shfl_down_sync(0xFFu, sacc, o);
        if (tid == 0) g_pd2[s][b][a] = sacc;
    }
}

// ---------------- kernel 4: reduce d2 + masked top-k selection (1 warp) ----------------
__global__ void k_select(const int* __restrict__ kptr) {
    const int tid = threadIdx.x;   // 32 threads
    __shared__ float d2s[B][A];
    if (tid < B * A) {
        const int b = tid >> 4, a = tid & 15;
        float v = 0.f;
#pragma unroll
        for (int s = 0; s < S_D2; s++) v += g_pd2[s][b][a];
        d2s[b][a] = v;
    }
    __syncwarp();
    if (tid == 0) {
        int k = kptr ? kptr[0] : 5;
        if (k > 16) k = 16;
        if (k < 0)  k = 0;
        for (int b = 0; b < B; b++) {
            float cd = g_cd2[b];
            float dv[16];
            int m = 0;
#pragma unroll
            for (int a = 0; a < A; a++) {
                dv[a] = d2s[b][a];
                if (dv[a] <= cd) m++;
            }
            bool used[16] = {false};
            int cnt = 0;
            for (int j = 0; j < k; j++) {
                int best = -1; float bv = INFINITY;
                for (int a = 0; a < A; a++) {
                    if (!used[a] && dv[a] <= cd && dv[a] < bv) { bv = dv[a]; best = a; }
                }
                if (best < 0) break;
                used[best] = true;
                g_selidx[b][cnt++] = best;
            }
            g_selcnt[b] = cnt;
            g_mcnt[b]   = m;
        }
    }
}

// ---------------- kernel 5: fused softmax-avg / argmax / confidence gate ----------------
__global__ __launch_bounds__(256) void k_final(const float* __restrict__ auged_logits,
                                               const float* __restrict__ tgt_logits,
                                               const int*   __restrict__ pseudo,
                                               float* __restrict__ out) {
    const int pix = blockIdx.x * 256 + threadIdx.x;   // < B*HW
    const int b = pix >> 16;
    const int p = pix & (HW - 1);

    const int cnt = g_selcnt[b];
    const int m   = g_mcnt[b];

    float acc[C];
#pragma unroll
    for (int c = 0; c < C; c++) acc[c] = 0.f;

    for (int j = 0; j < cnt; j++) {
        const int a = g_selidx[b][j];
        const float* __restrict__ lp = auged_logits + ((size_t)(b * A + a) * C) * HW + p;
        float l[C];
        float mx = -INFINITY;
#pragma unroll
        for (int c = 0; c < C; c++) { l[c] = lp[(size_t)c * HW]; mx = fmaxf(mx, l[c]); }
        float s = 0.f;
#pragma unroll
        for (int c = 0; c < C; c++) { l[c] = __expf(l[c] - mx); s += l[c]; }
        float inv = 1.0f / s;
#pragma unroll
        for (int c = 0; c < C; c++) acc[c] = fmaf(l[c], inv, acc[c]);
    }

    const float invc = 1.0f / (float)max(cnt, 1);

    // knn label = argmax over averaged softmax (first index on tie)
    int knn = 0; float bv = acc[0];
#pragma unroll
    for (int c = 1; c < C; c++) { if (acc[c] > bv) { bv = acc[c]; knn = c; } }

    // target confidence: max softmax prob = 1 / sum(exp(l - max))
    {
        const float* __restrict__ tp = tgt_logits + (size_t)b * C * HW + p;
        float mx = -INFINITY;
        float l[C];
#pragma unroll
        for (int c = 0; c < C; c++) { l[c] = tp[(size_t)c * HW]; mx = fmaxf(mx, l[c]); }
        float s = 0.f;
#pragma unroll
        for (int c = 0; c < C; c++) s += expf(l[c] - mx);
        float maxprob = 1.0f / s;
        bool pmask = maxprob < REFINE_CONF;

        int pl = pseudo[(size_t)b * HW + p];
        int refined = (pmask && m > 0) ? knn : pl;
        out[pix] = (float)refined;
    }

    // avg_soft output
    float* __restrict__ oavg = out + (size_t)B * HW;
#pragma unroll
    for (int c = 0; c < C; c++)
        oavg[((size_t)b * C + c) * HW + p] = acc[c] * invc;
}

// ---------------- launch ----------------
extern "C" void kernel_launch(void* const* d_in, const int* in_sizes, int n_in,
                              void* d_out, int out_size) {
    const float* source_queue = (const float*)d_in[0];
    const float* tgt_feat     = (const float*)d_in[1];
    const float* tgt_logits   = (const float*)d_in[2];
    const float* auged_feat   = (const float*)d_in[3];
    const float* auged_logits = (const float*)d_in[4];
    const int*   pseudo_label = (const int*)d_in[5];
    const int*   kptr         = (n_in > 6) ? (const int*)d_in[6] : nullptr;
    float* out = (float*)d_out;

    k_dots         <<<S_DOTS * NROWG, 256>>>(source_queue, tgt_feat);
    k_tt           <<<S_TT * B, 128>>>(tgt_feat);
    k_reduce_argmin<<<1, 512>>>();
    k_d2           <<<32 * S_D2, 256>>>(auged_feat, source_queue);
    k_select       <<<1, 32>>>(kptr);
    k_final        <<<(B * HW) / 256, 256>>>(auged_logits, tgt_logits, pseudo_label, out);
    (void)in_sizes; (void)out_size;
}